// round 12
// baseline (speedup 1.0000x reference)
#include <cuda_runtime.h>
#include <math.h>
#include <limits.h>

// CRF loss: out[b] = logZ(b) - label_score(b).  B=512, S=512, L=128.
//
// Scaled linear-space forward recursion, TWO adjacent-length batches per
// 256-thread block (R10 core). Lane layout: warp w, lane l -> jp = 8w+(l&7),
// quarter q = l>>3. Thread holds E rows [32q,32q+32) of columns {jp,jp+64}
// (32 f32x2 regs); each LDS.128 of U feeds 4 FFMA2. OWNER-DIRECTED
// reduction: 3 shfl instead of 8 (each lane keeps its owned (batch,col)
// partial and forwards the mirrored one). Every lane owns one
// (batch=q>>1, col=jp+64*(q&1)) scalar stream. U double-buffered in
// bank-skewed shared; ONE __syncthreads per step.
// Schedule: classic placement puts bid and bid+148 on one SM; the 40
// heaviest pairs go to the solo SMs (bid 108..147), dual SMs get pairs
// offset by 108 ranks.

#define LDIM 128

__device__ int d_perm[1024];

__device__ __forceinline__ unsigned long long pack_f32x2(float lo, float hi) {
    unsigned long long r;
    asm("mov.b64 %0, {%1, %2};" : "=l"(r) : "f"(lo), "f"(hi));
    return r;
}
__device__ __forceinline__ void unpack_f32x2(unsigned long long v, float& lo, float& hi) {
    asm("mov.b64 {%0, %1}, %2;" : "=f"(lo), "=f"(hi) : "l"(v));
}
__device__ __forceinline__ unsigned long long fma_f32x2(unsigned long long a,
                                                        unsigned long long b,
                                                        unsigned long long c) {
    unsigned long long d;
    asm("fma.rn.f32x2 %0, %1, %2, %3;" : "=l"(d) : "l"(a), "l"(b), "l"(c));
    return d;
}
__device__ __forceinline__ unsigned long long add_f32x2(unsigned long long a,
                                                        unsigned long long b) {
    unsigned long long d;
    asm("add.rn.f32x2 %0, %1, %2;" : "=l"(d) : "l"(a), "l"(b));
    return d;
}
__device__ __forceinline__ float rcp_approx(float x) {
    float r;
    asm("rcp.approx.ftz.f32 %0, %1;" : "=f"(r) : "f"(x));
    return r;
}
__device__ __forceinline__ float hsum2(unsigned long long a, unsigned long long b) {
    unsigned long long s = add_f32x2(a, b);
    float lo, hi;
    unpack_f32x2(s, lo, hi);
    return lo + hi;
}

// ------------- longest-first permutation (bitonic, 1 block) ---------------
__global__ void sort_len_kernel(const int* __restrict__ length, int B, int S)
{
    __shared__ int key[1024];
    __shared__ int val[1024];
    const int t = threadIdx.x;

    int k = INT_MAX;
    if (t < B) {
        int L = length[t];
        L = L < 1 ? 1 : (L > S ? S : L);
        k = -L;               // ascending on -len => longest first
    }
    key[t] = k;
    val[t] = t;
    __syncthreads();

    for (int kk = 2; kk <= 1024; kk <<= 1) {
        for (int s = kk >> 1; s > 0; s >>= 1) {
            int p = t ^ s;
            if (p > t) {
                bool up = ((t & kk) == 0);
                int kt = key[t], kp = key[p];
                if ((kt > kp) == up) {
                    key[t] = kp; key[p] = kt;
                    int vt = val[t]; val[t] = val[p]; val[p] = vt;
                }
            }
            __syncthreads();
        }
    }
    if (t < B) d_perm[t] = val[t];
}

// ------------------------------ main kernel --------------------------------
__global__ __launch_bounds__(256, 2)
void crf_forward_kernel(const float* __restrict__ input,
                        const int*   __restrict__ label,
                        const int*   __restrict__ length,
                        const float* __restrict__ trans,
                        float* __restrict__ out,
                        int S, int B, int npairs)
{
    __shared__ __align__(16) float u_sh[2][2][144];   // [buf][g][state]
    __shared__ float wred[2][8];
    __shared__ float wlog[2][8];
    __shared__ float s_x00[2];
    __shared__ float s_ls[2];

    const int tid = threadIdx.x;
    const int w   = tid >> 5;
    const int l   = tid & 31;
    const int q   = l >> 3;              // row quarter / ownership code
    const int jp  = w * 8 + (l & 7);     // column pair base 0..63
    const int g   = q >> 1;              // owned batch
    const int cb  = q & 1;               // owned column half
    const int jo  = jp + (cb << 6);      // owned column

    // schedule: classic placement -> SM hosts {bid, bid+148}; SMs 108..147
    // are solo. Heaviest 40 pairs -> solo SMs; dual SMs get partners
    // offset by 108 ranks.
    const int bid = blockIdx.x;
    int pid;
    if (npairs == 256) {
        if (bid >= 108 && bid < 148)      pid = bid - 108;   // pairs 0..39
        else if (bid < 108)               pid = 40 + bid;    // pairs 40..147
        else                              pid = bid;         // pairs 148..255
    } else {
        pid = bid;
    }

    const int  b0   = d_perm[2 * pid];
    const bool has1 = (2 * pid + 1 < B);
    const int  b1   = has1 ? d_perm[2 * pid + 1] : b0;

    int len0 = length[b0]; len0 = len0 < 1 ? 1 : (len0 > S ? S : len0);
    int len1 = len0;
    if (has1) { len1 = length[b1]; len1 = len1 < 1 ? 1 : (len1 > S ? S : len1); }
    // sorted order: len0 >= len1.

    const float* xb0 = input + (size_t)b0 * S * LDIM;
    const float* xb1 = input + (size_t)b1 * S * LDIM;
    const float* xbg = g ? xb1 : xb0;
    const int    lenown = g ? len1 : len0;

    // ---------------- label scores (both batches) ----------------------
    #pragma unroll
    for (int gg = 0; gg < 2; gg++) {
        const float* xb = gg ? xb1 : xb0;
        const int* labb = label + (size_t)(gg ? b1 : b0) * S;
        const int  len  = gg ? (has1 ? len1 : 0) : len0;
        float ls = 0.f;
        for (int t = tid; t < len; t += 256) {
            int lab = labb[t];
            ls += xb[(size_t)t * LDIM + lab];
            if (t + 1 < len) ls += trans[lab * LDIM + labb[t + 1]];
        }
        #pragma unroll
        for (int o = 16; o > 0; o >>= 1)
            ls += __shfl_xor_sync(0xffffffffu, ls, o);
        if (l == 0) wred[gg][w] = ls;
    }
    __syncthreads();
    if (tid < 2) {
        float acc = 0.f;
        #pragma unroll
        for (int i = 0; i < 8; i++) acc += wred[tid][i];
        s_ls[tid] = acc;
    }

    // --- E rows [32q,32q+32) of columns jp and jp+64: 32 f32x2 regs ----
    unsigned long long E2A[16], E2B[16];
    #pragma unroll
    for (int k = 0; k < 16; k++) {
        int i0 = 32 * q + 2 * k;
        E2A[k] = pack_f32x2(__expf(trans[(i0)     * LDIM + jp]),
                            __expf(trans[(i0 + 1) * LDIM + jp]));
        E2B[k] = pack_f32x2(__expf(trans[(i0)     * LDIM + jp + 64]),
                            __expf(trans[(i0 + 1) * LDIM + jp + 64]));
    }

    // ---------------- init U (every lane owns one (g, jo) stream) -------
    const int wido = jo + ((jo >> 5) << 2);   // skewed store index
    const float* pj = xbg + jo;
    float x0 = pj[0];
    if (tid == 0)  s_x00[0] = x0;             // g=0, jo=0
    if (tid == 16) s_x00[1] = x0;             // g=1, jo=0
    __syncthreads();
    float U = __expf(x0 - s_x00[g]);
    u_sh[0][g][wido] = U;

    const int omax = (lenown - 1) * LDIM;
    int o1 = LDIM     < omax ? LDIM     : omax;
    int o2 = 2 * LDIM < omax ? 2 * LDIM : omax;
    float xA = pj[o1];                         // x for t=1
    float xB = pj[o2];                         // x for t=2

    float alog = 0.f;                          // rotating owner lanes only
    __syncthreads();

    int cur = 0;

    // ---------------- forward recursion: t = 1 .. len0-1 ----------------
    for (int t = 1; t < len0; t++) {
        const int nxt = cur ^ 1;
        const float r  = rcp_approx(u_sh[cur][g][0]);   // own batch's U[0]
        const float ex = __expf(xA);

        // rotate prefetch (x for t+2)
        xA = xB;
        int on = (t + 2) * LDIM;
        if (on > omax) on = omax;
        xB = pj[on];

        // partial GEMVs: 8 LDS.128 per batch, each feeding 4 FFMA2
        const ulonglong2* p0 = (const ulonglong2*)(u_sh[cur][0] + 36 * q);
        const ulonglong2* p1 = (const ulonglong2*)(u_sh[cur][1] + 36 * q);
        unsigned long long aA0 = 0ull, aA1 = 0ull, aB0 = 0ull, aB1 = 0ull;
        unsigned long long cA0 = 0ull, cA1 = 0ull, cB0 = 0ull, cB1 = 0ull;
        #pragma unroll
        for (int c = 0; c < 8; c++) {
            ulonglong2 ua = p0[c];
            ulonglong2 va = p1[c];
            aA0 = fma_f32x2(ua.x, E2A[2 * c + 0], aA0);
            aA1 = fma_f32x2(ua.y, E2A[2 * c + 1], aA1);
            aB0 = fma_f32x2(ua.x, E2B[2 * c + 0], aB0);
            aB1 = fma_f32x2(ua.y, E2B[2 * c + 1], aB1);
            cA0 = fma_f32x2(va.x, E2A[2 * c + 0], cA0);
            cA1 = fma_f32x2(va.y, E2A[2 * c + 1], cA1);
            cB0 = fma_f32x2(va.x, E2B[2 * c + 0], cB0);
            cB1 = fma_f32x2(va.y, E2B[2 * c + 1], cB1);
        }
        float s0A = hsum2(aA0, aA1);   // batch0, col jp   (quarter partial)
        float s0B = hsum2(aB0, aB1);   // batch0, col jp+64
        float s1A = hsum2(cA0, cA1);   // batch1, col jp
        float s1B = hsum2(cB0, cB1);   // batch1, col jp+64

        // owner-directed reduction over quarters: 3 shfl total.
        // Stage xor8 (partner differs in col-class bit): keep own col
        // class per batch; send the mirrored partial -- partner's sent
        // register is exactly my needed partial.
        float k0 = cb ? s0B : s0A;
        float g0 = cb ? s0A : s0B;
        float k1 = cb ? s1B : s1A;
        float g1 = cb ? s1A : s1B;
        k0 += __shfl_xor_sync(0xffffffffu, g0, 8);
        k1 += __shfl_xor_sync(0xffffffffu, g1, 8);
        // Stage xor16 (partner differs in batch bit): keep own batch.
        float ko = g ? k1 : k0;
        float go = g ? k0 : k1;
        float sown = ko + __shfl_xor_sync(0xffffffffu, go, 16);

        float Un = sown * (r * ex);
        bool  act = (t < lenown);            // batch-1 freezes at len1
        U = act ? Un : U;
        u_sh[nxt][g][wido] = U;
        if ((l & 15) == 0 && w == (t & 7) && act)   // lanes 0,16 of warp t&7
            alog += __logf(r);
        cur = nxt;
        __syncthreads();
    }

    // ---------------- outputs ------------------------------------------
    float es0 = (g == 0) ? U : 0.f;
    float es1 = (g == 1) ? U : 0.f;
    #pragma unroll
    for (int oo = 16; oo > 0; oo >>= 1) {
        es0 += __shfl_xor_sync(0xffffffffu, es0, oo);
        es1 += __shfl_xor_sync(0xffffffffu, es1, oo);
    }
    if (l == 0)  { wred[0][w] = es0; wred[1][w] = es1; wlog[0][w] = alog; }
    if (l == 16) { wlog[1][w] = alog; }
    __syncthreads();
    if (tid == 0) {
        float ss0 = 0.f, al0 = 0.f;
        #pragma unroll
        for (int i = 0; i < 8; i++) { ss0 += wred[0][i]; al0 += wlog[0][i]; }
        out[b0] = s_x00[0] - al0 + logf(ss0) - s_ls[0];
        if (has1) {
            float ss1 = 0.f, al1 = 0.f;
            #pragma unroll
            for (int i = 0; i < 8; i++) { ss1 += wred[1][i]; al1 += wlog[1][i]; }
            out[b1] = s_x00[1] - al1 + logf(ss1) - s_ls[1];
        }
    }
}

extern "C" void kernel_launch(void* const* d_in, const int* in_sizes, int n_in,
                              void* d_out, int out_size)
{
    const float* input  = (const float*)d_in[0];   // (B, S, L) f32
    const int*   label  = (const int*)  d_in[1];   // (B, S) i32
    const int*   length = (const int*)  d_in[2];   // (B,) i32
    const float* trans  = (const float*)d_in[3];   // (L, L) f32
    float* out = (float*)d_out;                    // (B, 1) f32

    const int B = in_sizes[2];
    const int S = in_sizes[1] / B;

    const int npairs = (B + 1) / 2;

    sort_len_kernel<<<1, 1024>>>(length, B, S);
    crf_forward_kernel<<<npairs, 256>>>(input, label, length, trans, out,
                                        S, B, npairs);
}